// round 10
// baseline (speedup 1.0000x reference)
#include <cuda_runtime.h>
#include <cstdint>

#define ND 128
#define ED 64
#define HID 256
#define NMAX 100000
#define TM 64          // precompute rows per CTA
#define TME 32         // edge rows per CTA
#define NTHREADS 256

typedef unsigned long long ull;

__device__ __forceinline__ ull pack2(float lo, float hi) {
    ull r; asm("mov.b64 %0, {%1, %2};" : "=l"(r) : "f"(lo), "f"(hi)); return r;
}
__device__ __forceinline__ void fma2(ull &d, ull a, ull b) {
    asm("fma.rn.f32x2 %0, %1, %2, %0;" : "+l"(d) : "l"(a), "l"(b));
}
__device__ __forceinline__ ull add2(ull a, ull b) {
    ull r; asm("add.rn.f32x2 %0, %1, %2;" : "=l"(r) : "l"(a), "l"(b)); return r;
}
__device__ __forceinline__ float2 unpack2(ull v) {
    float2 f; asm("mov.b64 {%0, %1}, %2;" : "=f"(f.x), "=f"(f.y) : "l"(v)); return f;
}

// Per-node precomputed partials: Pa = x@W1a + b1, Pb = x@W1b
__device__ __align__(16) float g_Pa[(size_t)NMAX * HID];
__device__ __align__(16) float g_Pb[(size_t)NMAX * HID];

extern __shared__ float smem[];

// ============ Kernel 1: node precompute, both halves in one pass ===============
__global__ __launch_bounds__(NTHREADS, 2) void precompute_kernel(
    const float* __restrict__ x,
    const float* __restrict__ w1, const float* __restrict__ b1, int N)
{
    float* Xs = smem;              // [64][128] 32 KB
    float* Bs = smem + TM * ND;    // [64][256] 64 KB

    const int tid = threadIdx.x;
    const int tx  = tid & 31;
    const int ty  = tid >> 5;
    const int r0  = ty * 8;
    const int m0  = blockIdx.x * TM;

    int node[8];
    #pragma unroll
    for (int r = 0; r < 8; r++) {
        node[r] = min(m0 + r0 + r, N - 1);
        ((float4*)(Xs + (r0 + r) * ND))[tx] =
            ((const float4*)(x + (size_t)node[r] * ND))[tx];
    }

    for (int half = 0; half < 2; half++) {
        ull acc[8][4];
        if (half == 0) {
            ull bv[4];
            #pragma unroll
            for (int j = 0; j < 4; j++) {
                float2 b = ((const float2*)b1)[tx + 32 * j];
                bv[j] = pack2(b.x, b.y);
            }
            #pragma unroll
            for (int i = 0; i < 8; i++)
                #pragma unroll
                for (int j = 0; j < 4; j++) acc[i][j] = bv[j];
        } else {
            #pragma unroll
            for (int i = 0; i < 8; i++)
                #pragma unroll
                for (int j = 0; j < 4; j++) acc[i][j] = 0ull;
        }

        for (int kt = 0; kt < ND; kt += 64) {
            __syncthreads();
            const float4* wf4 = (const float4*)(w1 + (size_t)(half * ND + kt) * HID);
            #pragma unroll
            for (int it = 0; it < 16; it++) {
                int q = tid + it * NTHREADS;
                ((float4*)Bs)[q] = wf4[q];
            }
            __syncthreads();
            #pragma unroll 4
            for (int kk4 = 0; kk4 < 64; kk4 += 4) {
                float4 a4[8];
                #pragma unroll
                for (int i = 0; i < 8; i++)
                    a4[i] = *(const float4*)(Xs + (r0 + i) * ND + kt + kk4);
                #pragma unroll
                for (int kq = 0; kq < 4; kq++) {
                    const ull* Br = (const ull*)(Bs + (kk4 + kq) * HID) + tx;
                    ull b0 = Br[0], b1r = Br[32], b2r = Br[64], b3r = Br[96];
                    #pragma unroll
                    for (int i = 0; i < 8; i++) {
                        float a = (&a4[i].x)[kq];
                        ull aa = pack2(a, a);
                        fma2(acc[i][0], aa, b0);
                        fma2(acc[i][1], aa, b1r);
                        fma2(acc[i][2], aa, b2r);
                        fma2(acc[i][3], aa, b3r);
                    }
                }
            }
        }

        float* P = half ? g_Pb : g_Pa;
        #pragma unroll
        for (int i = 0; i < 8; i++) {
            float2* dst = (float2*)(P + (size_t)node[i] * HID);
            #pragma unroll
            for (int j = 0; j < 4; j++)
                dst[tx + 32 * j] = unpack2(acc[i][j]);
        }
    }
}

// ===================== Kernel 2: per-edge fused MLP + LN (TM=32, 3 CTAs/SM) =====
// SMEM: Es [32][64] 8 KB | Wbuf [32][256] 32 KB (W1c chunks, then h) | Cs [64][64] 16 KB
#define ES_OFF  0
#define WB_OFF  (TME * ED)
#define CS_OFF  (TME * ED + TME * HID)
#define EDGE_SMEM ((TME * ED + TME * HID + 64 * ED) * 4)   // 57344 B

__global__ __launch_bounds__(NTHREADS, 3) void edge_kernel(
    const int* __restrict__ ei32,
    const float* __restrict__ edge_attr,
    const float* __restrict__ w1,       // rows [256,320) = W1c
    const float* __restrict__ w2, const float* __restrict__ b2,
    const float* __restrict__ ln_w, const float* __restrict__ ln_b,
    float* __restrict__ out, int E, int N)
{
    float* Es   = smem + ES_OFF;
    float* Wbuf = smem + WB_OFF;
    float* Cs   = smem + CS_OFF;

    const int tid = threadIdx.x;
    const int tx  = tid & 31;
    const int w   = tid >> 5;           // 0..7
    const int r0  = w * 4;              // warp owns rows r0..r0+3
    const int e0  = blockIdx.x * TME;

    // int64/int32 detection
    unsigned oddbits = 0;
    #pragma unroll
    for (int k = 0; k < 16; k++) oddbits |= (unsigned)ei32[2 * k + 1];
    const int step = (oddbits == 0) ? 2 : 1;

    // stage W1c chunk0 (k rows 0..31) -> Wbuf
    {
        const float4* wf4 = (const float4*)(w1 + (size_t)(2 * ND) * HID);
        #pragma unroll
        for (int it = 0; it < 8; it++) {
            int q = tid + it * NTHREADS;   // 2048 float4
            ((float4*)Wbuf)[q] = wf4[q];
        }
    }

    // per-row: ea -> Es; acc = Pa[dst] + Pb[src]
    ull acc[4][4];
    #pragma unroll
    for (int i = 0; i < 4; i++) {
        int e = min(e0 + r0 + i, E - 1);
        int ss = ei32[(size_t)step * e];
        int ds = ei32[(size_t)step * (E + e)];
        ss = min(max(ss, 0), N - 1);
        ds = min(max(ds, 0), N - 1);
        if (tx < 16)
            ((float4*)(Es + (r0 + i) * ED))[tx] =
                ((const float4*)(edge_attr + (size_t)e * ED))[tx];
        const ull* pa = (const ull*)(g_Pa + (size_t)ds * HID) + tx;
        const ull* pb = (const ull*)(g_Pb + (size_t)ss * HID) + tx;
        #pragma unroll
        for (int j = 0; j < 4; j++)
            acc[i][j] = add2(pa[32 * j], pb[32 * j]);
    }
    __syncthreads();

    // -------- GEMM1 remainder: acc += ea @ W1c, two k-chunks of 32 --------
    #pragma unroll
    for (int ch = 0; ch < 2; ch++) {
        if (ch == 1) {
            __syncthreads();   // chunk0 reads done
            const float4* wf4 = (const float4*)(w1 + (size_t)(2 * ND + 32) * HID);
            #pragma unroll
            for (int it = 0; it < 8; it++) {
                int q = tid + it * NTHREADS;
                ((float4*)Wbuf)[q] = wf4[q];
            }
            __syncthreads();
        }
        #pragma unroll 4
        for (int kk4 = 0; kk4 < 32; kk4 += 4) {
            float4 a4[4];
            #pragma unroll
            for (int i = 0; i < 4; i++)
                a4[i] = *(const float4*)(Es + (r0 + i) * ED + ch * 32 + kk4);
            #pragma unroll
            for (int kq = 0; kq < 4; kq++) {
                const ull* Br = (const ull*)(Wbuf + (kk4 + kq) * HID) + tx;
                ull b0 = Br[0], b1r = Br[32], b2r = Br[64], b3r = Br[96];
                #pragma unroll
                for (int i = 0; i < 4; i++) {
                    float a = (&a4[i].x)[kq];
                    ull aa = pack2(a, a);
                    fma2(acc[i][0], aa, b0);
                    fma2(acc[i][1], aa, b1r);
                    fma2(acc[i][2], aa, b2r);
                    fma2(acc[i][3], aa, b3r);
                }
            }
        }
    }
    __syncthreads();   // all W1c reads done; Wbuf becomes h

    // h = relu(acc) -> Wbuf (own rows; conflict-free float2 stores)
    #pragma unroll
    for (int i = 0; i < 4; i++) {
        float* hr = Wbuf + (r0 + i) * HID;
        #pragma unroll
        for (int j = 0; j < 4; j++) {
            float2 v = unpack2(acc[i][j]);
            v.x = fmaxf(v.x, 0.f);
            v.y = fmaxf(v.y, 0.f);
            ((float2*)hr)[tx + 32 * j] = v;
        }
    }
    // no sync: GEMM2 A reads only own-warp h rows

    // -------- GEMM2: delta = h @ W2, 4 chunks of 64 k --------
    ull acc2[4];
    #pragma unroll
    for (int i = 0; i < 4; i++) acc2[i] = 0ull;

    for (int ch = 0; ch < 4; ch++) {
        __syncthreads();   // prev Cs reads done
        {
            const float4* src = (const float4*)(w2 + (size_t)(ch * 64) * ED);
            #pragma unroll
            for (int it = 0; it < 4; it++) {
                int q = tid + it * NTHREADS;   // 1024 float4 = [64][64]
                ((float4*)Cs)[q] = src[q];
            }
        }
        __syncthreads();
        #pragma unroll 4
        for (int kk4 = 0; kk4 < 64; kk4 += 4) {
            ull b[4];
            #pragma unroll
            for (int q = 0; q < 4; q++)
                b[q] = *((const ull*)(Cs + (kk4 + q) * ED) + tx);
            float4 a4[4];
            #pragma unroll
            for (int i = 0; i < 4; i++)
                a4[i] = *(const float4*)(Wbuf + (r0 + i) * HID + ch * 64 + kk4);
            #pragma unroll
            for (int q = 0; q < 4; q++) {
                #pragma unroll
                for (int i = 0; i < 4; i++) {
                    float a = (&a4[i].x)[q];
                    fma2(acc2[i], pack2(a, a), b[q]);
                }
            }
        }
    }

    // -------- Epilogue: residual + LayerNorm(64) + affine (cols {2tx,2tx+1}) ------
    float2 b2v = ((const float2*)b2)[tx];
    float2 lwv = ((const float2*)ln_w)[tx];
    float2 lbv = ((const float2*)ln_b)[tx];

    #pragma unroll
    for (int i = 0; i < 4; i++) {
        float2 d  = unpack2(acc2[i]);
        float2 ar = ((const float2*)(Es + (r0 + i) * ED))[tx];
        float v0 = ar.x + d.x + b2v.x;
        float v1 = ar.y + d.y + b2v.y;
        float s = v0 + v1;
        float q = v0 * v0 + v1 * v1;
        #pragma unroll
        for (int off = 16; off > 0; off >>= 1) {
            s += __shfl_xor_sync(0xffffffffu, s, off);
            q += __shfl_xor_sync(0xffffffffu, q, off);
        }
        float mean = s * 0.015625f;
        float var  = q * 0.015625f - mean * mean;
        float inv  = rsqrtf(var + 1e-5f);
        int e = e0 + r0 + i;
        if (e < E) {
            float2 o;
            o.x = (v0 - mean) * inv * lwv.x + lbv.x;
            o.y = (v1 - mean) * inv * lwv.y + lbv.y;
            ((float2*)(out + (size_t)e * ED))[tx] = o;
        }
    }
}

extern "C" void kernel_launch(void* const* d_in, const int* in_sizes, int n_in,
                              void* d_out, int out_size) {
    const float* x   = (const float*)d_in[0];
    const int*   ei  = (const int*)d_in[1];
    const float* ea  = (const float*)d_in[2];
    const float* w1  = (const float*)d_in[3];
    const float* b1  = (const float*)d_in[4];
    const float* w2  = (const float*)d_in[5];
    const float* b2  = (const float*)d_in[6];
    const float* lnw = (const float*)d_in[7];
    const float* lnb = (const float*)d_in[8];
    float* out = (float*)d_out;

    int E = in_sizes[1] / 2;
    int N = in_sizes[0] / ND;

    static int init_done = 0;
    int smem_pre = (TM * ND + TM * HID) * (int)sizeof(float);   // 98304
    if (!init_done) {
        cudaFuncSetAttribute(precompute_kernel,
                             cudaFuncAttributeMaxDynamicSharedMemorySize, smem_pre);
        cudaFuncSetAttribute(edge_kernel,
                             cudaFuncAttributeMaxDynamicSharedMemorySize, EDGE_SMEM);
        init_done = 1;
    }

    int pgrid = (N + TM - 1) / TM;
    precompute_kernel<<<pgrid, NTHREADS, smem_pre>>>(x, w1, b1, N);

    int egrid = (E + TME - 1) / TME;
    edge_kernel<<<egrid, NTHREADS, EDGE_SMEM>>>(
        ei, ea, w1, w2, b2, lnw, lnb, out, E, N);
}

// round 12
// speedup vs baseline: 1.1817x; 1.1817x over previous
#include <cuda_runtime.h>
#include <cstdint>

#define ND 128
#define ED 64
#define HID 256
#define NMAX 100000
#define TM 64
#define NTHREADS 256

typedef unsigned long long ull;

__device__ __forceinline__ ull pack2(float lo, float hi) {
    ull r; asm("mov.b64 %0, {%1, %2};" : "=l"(r) : "f"(lo), "f"(hi)); return r;
}
__device__ __forceinline__ void fma2(ull &d, ull a, ull b) {
    asm("fma.rn.f32x2 %0, %1, %2, %0;" : "+l"(d) : "l"(a), "l"(b));
}
__device__ __forceinline__ ull add2(ull a, ull b) {
    ull r; asm("add.rn.f32x2 %0, %1, %2;" : "=l"(r) : "l"(a), "l"(b)); return r;
}
__device__ __forceinline__ float2 unpack2(ull v) {
    float2 f; asm("mov.b64 {%0, %1}, %2;" : "=f"(f.x), "=f"(f.y) : "l"(v)); return f;
}
__device__ __forceinline__ ull relu2(ull v) {
    float2 f = unpack2(v);
    return pack2(fmaxf(f.x, 0.f), fmaxf(f.y, 0.f));
}

// Per-node precomputed partials: Pa = x@W1a + b1, Pb = x@W1b
__device__ __align__(16) float g_Pa[(size_t)NMAX * HID];
__device__ __align__(16) float g_Pb[(size_t)NMAX * HID];

extern __shared__ float smem[];

// ============ Kernel 1: node precompute, both halves in one pass ===============
// Column ownership: cols {4tx..4tx+3} and {128+4tx..131}  (all 128-bit accesses)
__global__ __launch_bounds__(NTHREADS, 2) void precompute_kernel(
    const float* __restrict__ x,
    const float* __restrict__ w1, const float* __restrict__ b1, int N)
{
    float* Xs = smem;              // [64][128] 32 KB
    float* Bs = smem + TM * ND;    // [64][256] 64 KB

    const int tid = threadIdx.x;
    const int tx  = tid & 31;
    const int ty  = tid >> 5;
    const int r0  = ty * 8;
    const int m0  = blockIdx.x * TM;

    int node[8];
    #pragma unroll
    for (int r = 0; r < 8; r++) {
        node[r] = min(m0 + r0 + r, N - 1);
        ((float4*)(Xs + (r0 + r) * ND))[tx] =
            ((const float4*)(x + (size_t)node[r] * ND))[tx];
    }

    for (int half = 0; half < 2; half++) {
        ull acc[8][4];
        if (half == 0) {
            ulonglong2 bvA = ((const ulonglong2*)b1)[tx];
            ulonglong2 bvB = ((const ulonglong2*)b1)[tx + 32];
            #pragma unroll
            for (int i = 0; i < 8; i++) {
                acc[i][0] = bvA.x; acc[i][1] = bvA.y;
                acc[i][2] = bvB.x; acc[i][3] = bvB.y;
            }
        } else {
            #pragma unroll
            for (int i = 0; i < 8; i++)
                #pragma unroll
                for (int j = 0; j < 4; j++) acc[i][j] = 0ull;
        }

        for (int kt = 0; kt < ND; kt += 64) {
            __syncthreads();
            const float4* wf4 = (const float4*)(w1 + (size_t)(half * ND + kt) * HID);
            #pragma unroll
            for (int it = 0; it < 16; it++) {
                int q = tid + it * NTHREADS;
                ((float4*)Bs)[q] = wf4[q];
            }
            __syncthreads();
            #pragma unroll 4
            for (int kk4 = 0; kk4 < 64; kk4 += 4) {
                float4 a4[8];
                #pragma unroll
                for (int i = 0; i < 8; i++)
                    a4[i] = *(const float4*)(Xs + (r0 + i) * ND + kt + kk4);
                #pragma unroll
                for (int kq = 0; kq < 4; kq++) {
                    const ulonglong2* Br = (const ulonglong2*)(Bs + (kk4 + kq) * HID);
                    ulonglong2 bA = Br[tx];        // cols 4tx..4tx+3
                    ulonglong2 bB = Br[tx + 32];   // cols 128+4tx..131
                    #pragma unroll
                    for (int i = 0; i < 8; i++) {
                        float a = (&a4[i].x)[kq];
                        ull aa = pack2(a, a);
                        fma2(acc[i][0], aa, bA.x);
                        fma2(acc[i][1], aa, bA.y);
                        fma2(acc[i][2], aa, bB.x);
                        fma2(acc[i][3], aa, bB.y);
                    }
                }
            }
        }

        float* P = half ? g_Pb : g_Pa;
        #pragma unroll
        for (int i = 0; i < 8; i++) {
            ulonglong2* dst = (ulonglong2*)(P + (size_t)node[i] * HID);
            dst[tx]      = make_ulonglong2(acc[i][0], acc[i][1]);
            dst[tx + 32] = make_ulonglong2(acc[i][2], acc[i][3]);
        }
    }
}

// ===================== Kernel 2: per-edge fused MLP + LN ========================
// SMEM: Es [64][64] 16 KB | Ws [64][256] (W1c then h) 64 KB | Cs [64][64] 16 KB
#define EDGE_SMEM ((TM * ED + TM * HID + TM * ED) * 4)   // 98304 B

__global__ __launch_bounds__(NTHREADS, 2) void edge_kernel(
    const int* __restrict__ ei32,
    const float* __restrict__ edge_attr,
    const float* __restrict__ w1,       // rows [256,320) = W1c
    const float* __restrict__ w2, const float* __restrict__ b2,
    const float* __restrict__ ln_w, const float* __restrict__ ln_b,
    float* __restrict__ out, int E, int N)
{
    float* Es = smem;
    float* Ws = smem + TM * ED;
    float* Cs = smem + TM * ED + TM * HID;

    const int tid = threadIdx.x;
    const int tx  = tid & 31;
    const int ty  = tid >> 5;
    const int r0  = ty * 8;
    const int e0  = blockIdx.x * TM;

    // int64/int32 detection
    unsigned oddbits = 0;
    #pragma unroll
    for (int k = 0; k < 16; k++) oddbits |= (unsigned)ei32[2 * k + 1];
    const int step = (oddbits == 0) ? 2 : 1;

    // W1c tile -> Ws [64][256]
    {
        const float4* wf4 = (const float4*)(w1 + (size_t)(2 * ND) * HID);
        #pragma unroll
        for (int it = 0; it < 16; it++) {
            int q = tid + it * NTHREADS;
            ((float4*)Ws)[q] = wf4[q];
        }
    }

    // per-row: ea -> Es; acc = Pa[dst] + Pb[src]  (all LDG.128)
    ull acc[8][4];
    #pragma unroll
    for (int r = 0; r < 8; r++) {
        int e = min(e0 + r0 + r, E - 1);
        int ss = ei32[(size_t)step * e];
        int ds = ei32[(size_t)step * (E + e)];
        ss = min(max(ss, 0), N - 1);
        ds = min(max(ds, 0), N - 1);
        if (tx < 16)
            ((float4*)(Es + (r0 + r) * ED))[tx] =
                ((const float4*)(edge_attr + (size_t)e * ED))[tx];
        const ulonglong2* pa = (const ulonglong2*)(g_Pa + (size_t)ds * HID);
        const ulonglong2* pb = (const ulonglong2*)(g_Pb + (size_t)ss * HID);
        ulonglong2 a0 = pa[tx],      b0 = pb[tx];
        ulonglong2 a1 = pa[tx + 32], b1v = pb[tx + 32];
        acc[r][0] = add2(a0.x, b0.x);
        acc[r][1] = add2(a0.y, b0.y);
        acc[r][2] = add2(a1.x, b1v.x);
        acc[r][3] = add2(a1.y, b1v.y);
    }
    __syncthreads();

    // -------- GEMM1 remainder: acc += ea @ W1c (K = 64), LDS.128 B reads --------
    #pragma unroll 4
    for (int kk4 = 0; kk4 < ED; kk4 += 4) {
        float4 a4[8];
        #pragma unroll
        for (int i = 0; i < 8; i++)
            a4[i] = *(const float4*)(Es + (r0 + i) * ED + kk4);
        #pragma unroll
        for (int kq = 0; kq < 4; kq++) {
            const ulonglong2* Br = (const ulonglong2*)(Ws + (kk4 + kq) * HID);
            ulonglong2 bA = Br[tx];
            ulonglong2 bB = Br[tx + 32];
            #pragma unroll
            for (int i = 0; i < 8; i++) {
                float a = (&a4[i].x)[kq];
                ull aa = pack2(a, a);
                fma2(acc[i][0], aa, bA.x);
                fma2(acc[i][1], aa, bA.y);
                fma2(acc[i][2], aa, bB.x);
                fma2(acc[i][3], aa, bB.y);
            }
        }
    }
    __syncthreads();   // W1c reads done; Ws becomes h

    // h = relu(acc) -> Ws (own rows; STS.128)
    #pragma unroll
    for (int i = 0; i < 8; i++) {
        ulonglong2* hr = (ulonglong2*)(Ws + (r0 + i) * HID);
        hr[tx]      = make_ulonglong2(relu2(acc[i][0]), relu2(acc[i][1]));
        hr[tx + 32] = make_ulonglong2(relu2(acc[i][2]), relu2(acc[i][3]));
    }

    // -------- GEMM2: delta = h @ W2 (K = 256, 4 chunks of 64) --------
    ull acc2[8];
    #pragma unroll
    for (int i = 0; i < 8; i++) acc2[i] = 0ull;

    for (int kt = 0; kt < HID; kt += 64) {
        __syncthreads();   // h stores visible / prev Cs reads done
        const float4* w2f4 = (const float4*)(w2 + (size_t)kt * ED);
        #pragma unroll
        for (int it = 0; it < 4; it++) {
            int q = tid + it * NTHREADS;   // 1024 float4 = [64][64]
            ((float4*)Cs)[q] = w2f4[q];
        }
        __syncthreads();
        #pragma unroll 4
        for (int kk4 = 0; kk4 < 64; kk4 += 4) {
            float4 a4[8];
            #pragma unroll
            for (int i = 0; i < 8; i++)
                a4[i] = *(const float4*)(Ws + (r0 + i) * HID + kt + kk4);
            #pragma unroll
            for (int kq = 0; kq < 4; kq++) {
                ull b = *((const ull*)(Cs + (kk4 + kq) * ED) + tx);
                #pragma unroll
                for (int i = 0; i < 8; i++) {
                    float a = (&a4[i].x)[kq];
                    fma2(acc2[i], pack2(a, a), b);
                }
            }
        }
    }

    // -------- Epilogue: residual + LayerNorm(64) + affine (cols {2tx,2tx+1}) ------
    float2 b2v = ((const float2*)b2)[tx];
    float2 lwv = ((const float2*)ln_w)[tx];
    float2 lbv = ((const float2*)ln_b)[tx];

    #pragma unroll
    for (int i = 0; i < 8; i++) {
        float2 d  = unpack2(acc2[i]);
        float2 ar = ((const float2*)(Es + (r0 + i) * ED))[tx];
        float v0 = ar.x + d.x + b2v.x;
        float v1 = ar.y + d.y + b2v.y;
        float s = v0 + v1;
        float q = v0 * v0 + v1 * v1;
        #pragma unroll
        for (int off = 16; off > 0; off >>= 1) {
            s += __shfl_xor_sync(0xffffffffu, s, off);
            q += __shfl_xor_sync(0xffffffffu, q, off);
        }
        float mean = s * 0.015625f;
        float var  = q * 0.015625f - mean * mean;
        float inv  = rsqrtf(var + 1e-5f);
        int e = e0 + r0 + i;
        if (e < E) {
            float2 o;
            o.x = (v0 - mean) * inv * lwv.x + lbv.x;
            o.y = (v1 - mean) * inv * lwv.y + lbv.y;
            ((float2*)(out + (size_t)e * ED))[tx] = o;
        }
    }
}

extern "C" void kernel_launch(void* const* d_in, const int* in_sizes, int n_in,
                              void* d_out, int out_size) {
    const float* x   = (const float*)d_in[0];
    const int*   ei  = (const int*)d_in[1];
    const float* ea  = (const float*)d_in[2];
    const float* w1  = (const float*)d_in[3];
    const float* b1  = (const float*)d_in[4];
    const float* w2  = (const float*)d_in[5];
    const float* b2  = (const float*)d_in[6];
    const float* lnw = (const float*)d_in[7];
    const float* lnb = (const float*)d_in[8];
    float* out = (float*)d_out;

    int E = in_sizes[1] / 2;
    int N = in_sizes[0] / ND;

    static int init_done = 0;
    int smem_pre = (TM * ND + TM * HID) * (int)sizeof(float);   // 98304
    if (!init_done) {
        cudaFuncSetAttribute(precompute_kernel,
                             cudaFuncAttributeMaxDynamicSharedMemorySize, smem_pre);
        cudaFuncSetAttribute(edge_kernel,
                             cudaFuncAttributeMaxDynamicSharedMemorySize, EDGE_SMEM);
        init_done = 1;
    }

    int pgrid = (N + TM - 1) / TM;
    precompute_kernel<<<pgrid, NTHREADS, smem_pre>>>(x, w1, b1, N);

    int egrid = (E + TM - 1) / TM;
    edge_kernel<<<egrid, NTHREADS, EDGE_SMEM>>>(
        ei, ea, w1, w2, b2, lnw, lnb, out, E, N);
}